// round 7
// baseline (speedup 1.0000x reference)
#include <cuda_runtime.h>

#define NTHREADS 256
#define TS 1028                  // tile row stride (4 mod 32 -> conflict-free frag loads)
#define HS 68                    // hbuf row stride

// per-block weight slab in smem (floats):
//   [0,2176)    w1hi (2048 used)  -- aliased by hbuf (32*68=2176) after mm1
//   [2176,4224) w2hi (2048)
//   [4224,4288) b1 (64)
//   [4288,4320) b2 (32)
#define WSLAB 4352
#define SM_TILE 0
#define SM_W    32896            // 32*1028
#define SM_TOTAL (SM_W + 4 * WSLAB)   // 50304 floats = 201216 B

typedef unsigned long long u64;
typedef unsigned int u32;

// pre-split fragment-packed weights: [layer][block][cell 32][lane 32][2]
__device__ float g_w1hi[2 * 32 * 2048];
__device__ float g_w1lo[2 * 32 * 2048];
__device__ float g_w2hi[2 * 32 * 2048];
__device__ float g_w2lo[2 * 32 * 2048];

__device__ __forceinline__ u64 pack2(float lo, float hi) {
    u64 r; asm("mov.b64 %0, {%1, %2};" : "=l"(r) : "f"(lo), "f"(hi)); return r;
}
__device__ __forceinline__ void unpack2(u64 v, float& lo, float& hi) {
    asm("mov.b64 {%0, %1}, %2;" : "=f"(lo), "=f"(hi) : "l"(v));
}
__device__ __forceinline__ u32 s2u(const void* p) {
    u32 r;
    asm("{.reg .u64 t; cvta.to.shared.u64 t, %1; cvt.u32.u64 %0, t;}" : "=r"(r) : "l"(p));
    return r;
}
__device__ __forceinline__ void cpa16(u32 dst, const float* src) {
    asm volatile("cp.async.cg.shared.global [%0], [%1], 16;" :: "r"(dst), "l"(src));
}
__device__ __forceinline__ u32 f2tf(float f) {
    u32 u; asm("cvt.rna.tf32.f32 %0, %1;" : "=r"(u) : "f"(f)); return u;
}
__device__ __forceinline__ void split(float f, u32& h, u32& l) {
    h = f2tf(f);
    l = __float_as_uint(f - __uint_as_float(h));
}
__device__ __forceinline__ void mma8(float* c, const u32* a, u32 b0, u32 b1) {
    asm volatile(
        "mma.sync.aligned.m16n8k8.row.col.f32.tf32.tf32.f32 "
        "{%0,%1,%2,%3}, {%4,%5,%6,%7}, {%8,%9}, {%0,%1,%2,%3};"
        : "+f"(c[0]), "+f"(c[1]), "+f"(c[2]), "+f"(c[3])
        : "r"(a[0]), "r"(a[1]), "r"(a[2]), "r"(a[3]), "r"(b0), "r"(b1));
}
__device__ __forceinline__ float elu(float v) {
    return v > 0.f ? v : (__expf(v) - 1.f);
}

// ---- prep: split weights into tf32 hi/lo, fragment-packed ----
__global__ void prep_kernel(
    const float* __restrict__ W1a, const float* __restrict__ W2a,
    const float* __restrict__ W1b, const float* __restrict__ W2b)
{
    int id = blockIdx.x * blockDim.x + threadIdx.x;   // 131072 total
    int lane = id & 31;
    int cell = (id >> 5) & 31;
    int b    = (id >> 10) & 31;
    int mat  = (id >> 15) & 1;
    int l    = id >> 16;
    int g = lane >> 2, t4 = lane & 3;
    float v0, v1;
    if (mat == 0) {
        int nt = cell >> 2, kt = cell & 3;
        int k0 = kt * 8 + t4, n = nt * 8 + g;
        const float* W = (l ? W1b : W1a) + b * 2048;
        v0 = W[k0 * 64 + n];
        v1 = W[(k0 + 4) * 64 + n];
    } else {
        int nt = cell >> 3, kt = cell & 7;
        int k0 = kt * 8 + t4, n = nt * 8 + g;
        const float* W = (l ? W2b : W2a) + b * 2048;
        v0 = W[k0 * 32 + n];
        v1 = W[(k0 + 4) * 32 + n];
    }
    float h0 = __uint_as_float(f2tf(v0));
    float h1 = __uint_as_float(f2tf(v1));
    int oi = (((l * 32 + b) * 32 + cell) * 32 + lane) * 2;
    float* hi = mat ? g_w2hi : g_w1hi;
    float* lo = mat ? g_w2lo : g_w1lo;
    hi[oi] = h0;      hi[oi + 1] = h1;
    lo[oi] = v0 - h0; lo[oi + 1] = v1 - h1;
}

// in-place per-row 32x32 block transpose
__device__ __forceinline__ void transpose_tile(float* tile, int warp, int lane) {
    const int a2 = lane >> 3;
    const int B  = lane & 7;
    #pragma unroll
    for (int rr = 0; rr < 4; ++rr) {
        float* row = tile + (warp * 4 + rr) * TS;
        float4 v[2][4];
        #pragma unroll
        for (int h = 0; h < 2; ++h) {
            int A = a2 + 4 * h;
            #pragma unroll
            for (int i = 0; i < 4; ++i)
                v[h][i] = *(const float4*)(row + 32 * (4 * A + i) + 4 * B);
        }
        __syncwarp();
        #pragma unroll
        for (int h = 0; h < 2; ++h) {
            int A = a2 + 4 * h;
            #pragma unroll
            for (int i = 0; i < 4; ++i) {
                float4 t;
                t.x = ((const float*)&v[h][0])[i];
                t.y = ((const float*)&v[h][1])[i];
                t.z = ((const float*)&v[h][2])[i];
                t.w = ((const float*)&v[h][3])[i];
                *(float4*)(row + 32 * (4 * B + i) + 4 * A) = t;
            }
        }
        __syncwarp();
    }
}

__global__ __launch_bounds__(NTHREADS, 1) void mixer_kernel(
    const float* __restrict__ x,
    const float* __restrict__ B1a, const float* __restrict__ B2a,
    const float* __restrict__ B1b, const float* __restrict__ B2b,
    float* __restrict__ out)
{
    extern __shared__ float smem[];
    float* tile = smem + SM_TILE;

    const int tid  = threadIdx.x;
    const int warp = tid >> 5;
    const int lane = tid & 31;
    const int nb   = warp >> 1;           // block within stage (0..3)
    const int mh   = warp & 1;            // row half
    const int g    = lane >> 2;
    const int t4   = lane & 3;
    const int mrow = mh * 16 + g;
    const int ptid = mh * 32 + lane;      // 0..63 within pair
    const long row0 = (long)blockIdx.x * 32;

    float* slab = smem + SM_W + nb * WSLAB;
    const u32 slab_u = s2u(slab);

    const float* B1p[2] = {B1a, B1b};
    const float* B2p[2] = {B2a, B2b};

    // stage block weights (hi frags + biases) for stage si into this pair's slab
    auto stage_issue = [&](int si) {
        const int layer = si >> 3;
        const int blk   = (si & 7) * 4 + nb;
        const int lb    = layer * 32 + blk;
        const float* s1 = g_w1hi + (size_t)lb * 2048;
        const float* s2 = g_w2hi + (size_t)lb * 2048;
        #pragma unroll
        for (int j = 0; j < 8; ++j) {
            int c = ptid + j * 64;
            cpa16(slab_u + (u32)c * 16u,           s1 + c * 4);
            cpa16(slab_u + 8704u + (u32)c * 16u,   s2 + c * 4);
        }
        if (ptid < 16)      cpa16(slab_u + 16896u + (u32)ptid * 16u, B1p[layer] + blk * 64 + ptid * 4);
        else if (ptid < 24) cpa16(slab_u + 17152u + (u32)(ptid - 16) * 16u, B2p[layer] + blk * 32 + (ptid - 16) * 4);
        asm volatile("cp.async.commit_group;");
    };

    stage_issue(0);

    // load x tile
    {
        const float4* src = (const float4*)(x + row0 * 1024);
        #pragma unroll
        for (int it = 0; it < 32; ++it) {
            int i = tid + it * NTHREADS;
            int r = i >> 8, c4 = i & 255;
            *(float4*)(tile + r * TS + c4 * 4) = src[r * 256 + c4];
        }
    }
    __syncthreads();

    for (int si = 0; si < 16; ++si) {
        if (si == 8) {
            __syncthreads();
            transpose_tile(tile, warp, lane);
            __syncthreads();
        }
        asm volatile("cp.async.wait_group 0;");
        asm volatile("bar.sync %0, 64;" :: "r"(nb + 1) : "memory");

        const int layer = si >> 3;
        const int blk   = (si & 7) * 4 + nb;
        const int lb    = layer * 32 + blk;
        const int cbase = blk * 32;
        const u64* lo1 = (const u64*)(g_w1lo + (size_t)lb * 2048) + lane;
        const u64* lo2 = (const u64*)(g_w2lo + (size_t)lb * 2048) + lane;

        // ---- A-fragments (x split) ----
        u32 ah[4][4], al[4][4];
        {
            const float* xr = tile + mrow * TS + cbase;
            #pragma unroll
            for (int kt = 0; kt < 4; ++kt) {
                split(xr[kt * 8 + t4],               ah[kt][0], al[kt][0]);
                split(xr[8 * TS + kt * 8 + t4],      ah[kt][1], al[kt][1]);
                split(xr[kt * 8 + t4 + 4],           ah[kt][2], al[kt][2]);
                split(xr[8 * TS + kt * 8 + t4 + 4],  ah[kt][3], al[kt][3]);
            }
        }

        // ---- matmul1: 16 rows x 64 hidden ----
        float c1[8][4];
        #pragma unroll
        for (int nt = 0; nt < 8; ++nt) {
            float blo, bhi;
            unpack2(*(const u64*)(slab + 4224 + nt * 8 + 2 * t4), blo, bhi);
            c1[nt][0] = blo; c1[nt][1] = bhi; c1[nt][2] = blo; c1[nt][3] = bhi;
        }
        #pragma unroll
        for (int nt = 0; nt < 8; ++nt) {
            u64 blf[4];
            #pragma unroll
            for (int kt = 0; kt < 4; ++kt) blf[kt] = lo1[(nt * 4 + kt) * 32];
            #pragma unroll
            for (int kt = 0; kt < 4; ++kt) {
                u64 bhf = *(const u64*)(slab + (nt * 4 + kt) * 64 + lane * 2);
                u32 bh0 = (u32)bhf, bh1 = (u32)(bhf >> 32);
                u32 bl0 = (u32)blf[kt], bl1 = (u32)(blf[kt] >> 32);
                mma8(c1[nt], ah[kt], bh0, bh1);
                mma8(c1[nt], al[kt], bh0, bh1);
                mma8(c1[nt], ah[kt], bl0, bl1);
            }
        }
        // pair done reading w1hi -> safe to overwrite with h
        asm volatile("bar.sync %0, 64;" :: "r"(nb + 1) : "memory");

        // ---- ELU + stage h (warp-local region of slab[0,2176)) ----
        #pragma unroll
        for (int nt = 0; nt < 8; ++nt) {
            float e0 = elu(c1[nt][0]), e1 = elu(c1[nt][1]);
            float e2 = elu(c1[nt][2]), e3 = elu(c1[nt][3]);
            *(u64*)(slab + mrow * HS + nt * 8 + 2 * t4)       = pack2(e0, e1);
            *(u64*)(slab + (mrow + 8) * HS + nt * 8 + 2 * t4) = pack2(e2, e3);
        }
        __syncwarp();

        // ---- matmul2: 16 rows x 32 out (+bias+residual) ----
        float c2[4][4];
        {
            const float* resp = tile + mrow * TS + cbase;
            #pragma unroll
            for (int nt = 0; nt < 4; ++nt) {
                float blo, bhi, r0l, r0h, r1l, r1h;
                unpack2(*(const u64*)(slab + 4288 + nt * 8 + 2 * t4), blo, bhi);
                unpack2(*(const u64*)(resp + nt * 8 + 2 * t4), r0l, r0h);
                unpack2(*(const u64*)(resp + 8 * TS + nt * 8 + 2 * t4), r1l, r1h);
                c2[nt][0] = blo + r0l; c2[nt][1] = bhi + r0h;
                c2[nt][2] = blo + r1l; c2[nt][3] = bhi + r1h;
            }
        }
        #pragma unroll
        for (int kt = 0; kt < 8; ++kt) {
            u32 ah2[4], al2[4];
            split(slab[mrow * HS + kt * 8 + t4],             ah2[0], al2[0]);
            split(slab[(mrow + 8) * HS + kt * 8 + t4],       ah2[1], al2[1]);
            split(slab[mrow * HS + kt * 8 + t4 + 4],         ah2[2], al2[2]);
            split(slab[(mrow + 8) * HS + kt * 8 + t4 + 4],   ah2[3], al2[3]);
            u64 blf[4];
            #pragma unroll
            for (int nt = 0; nt < 4; ++nt) blf[nt] = lo2[(nt * 8 + kt) * 32];
            #pragma unroll
            for (int nt = 0; nt < 4; ++nt) {
                u64 bhf = *(const u64*)(slab + 2176 + (nt * 8 + kt) * 64 + lane * 2);
                u32 bh0 = (u32)bhf, bh1 = (u32)(bhf >> 32);
                u32 bl0 = (u32)blf[nt], bl1 = (u32)(blf[nt] >> 32);
                mma8(c2[nt], ah2, bh0, bh1);
                mma8(c2[nt], al2, bh0, bh1);
                mma8(c2[nt], ah2, bl0, bl1);
            }
        }
        {
            float* resp = tile + mrow * TS + cbase;
            #pragma unroll
            for (int nt = 0; nt < 4; ++nt) {
                *(u64*)(resp + nt * 8 + 2 * t4)          = pack2(c2[nt][0], c2[nt][1]);
                *(u64*)(resp + 8 * TS + nt * 8 + 2 * t4) = pack2(c2[nt][2], c2[nt][3]);
            }
        }
        // pair done with slab (w2hi + hbuf) -> refill for next stage
        asm volatile("bar.sync %0, 64;" :: "r"(nb + 1) : "memory");
        if (si < 15) stage_issue(si + 1);
    }

    __syncthreads();
    transpose_tile(tile, warp, lane);
    __syncthreads();

    // store output
    {
        float4* dst = (float4*)(out + row0 * 1024);
        #pragma unroll
        for (int it = 0; it < 32; ++it) {
            int i = tid + it * NTHREADS;
            int r = i >> 8, c4 = i & 255;
            dst[r * 256 + c4] = *(const float4*)(tile + r * TS + c4 * 4);
        }
    }
}

extern "C" void kernel_launch(void* const* d_in, const int* in_sizes, int n_in,
                              void* d_out, int out_size) {
    const float* x   = (const float*)d_in[0];
    const float* W1a = (const float*)d_in[1];
    const float* B1a = (const float*)d_in[2];
    const float* W2a = (const float*)d_in[3];
    const float* B2a = (const float*)d_in[4];
    const float* W1b = (const float*)d_in[5];
    const float* B1b = (const float*)d_in[6];
    const float* W2b = (const float*)d_in[7];
    const float* B2b = (const float*)d_in[8];
    float* out = (float*)d_out;

    int rows = in_sizes[0] / 1024;
    int grid = rows / 32;                       // 512

    size_t smem_bytes = (size_t)SM_TOTAL * sizeof(float);   // 201216 B
    static int configured = -1;
    if (configured < 0) {
        cudaFuncSetAttribute(mixer_kernel,
                             cudaFuncAttributeMaxDynamicSharedMemorySize,
                             (int)smem_bytes);
        configured = 1;
    }

    prep_kernel<<<512, 256>>>(W1a, W2a, W1b, W2b);
    mixer_kernel<<<grid, NTHREADS, smem_bytes>>>(
        x, B1a, B2a, B1b, B2b, out);
}

// round 8
// speedup vs baseline: 1.5842x; 1.5842x over previous
#include <cuda_runtime.h>

#define NTHREADS 256
#define TS 1028                  // tile row stride (4 mod 32 -> conflict-free frag loads)
#define HS 68                    // hbuf row stride
#define ROWS 16

// smem (floats): tile 16*1028 = 16448 | per-warp hbuf 8 * (16*68=1088) = 8704
#define SM_TILE 0
#define SM_HB   16448
#define SM_TOTAL (SM_HB + 8 * 1088)   // 25152 floats = 100608 B

typedef unsigned long long u64;
typedef unsigned int u32;

// pre-split fragment-packed weights: [layer][block][cell 32][lane 32][2]
__device__ float g_w1hi[2 * 32 * 2048];
__device__ float g_w1lo[2 * 32 * 2048];
__device__ float g_w2hi[2 * 32 * 2048];
__device__ float g_w2lo[2 * 32 * 2048];

__device__ __forceinline__ u64 pack2(float lo, float hi) {
    u64 r; asm("mov.b64 %0, {%1, %2};" : "=l"(r) : "f"(lo), "f"(hi)); return r;
}
__device__ __forceinline__ void unpack2(u64 v, float& lo, float& hi) {
    asm("mov.b64 {%0, %1}, %2;" : "=f"(lo), "=f"(hi) : "l"(v));
}
__device__ __forceinline__ u32 f2tf(float f) {
    u32 u; asm("cvt.rna.tf32.f32 %0, %1;" : "=r"(u) : "f"(f)); return u;
}
__device__ __forceinline__ void split(float f, u32& h, u32& l) {
    h = f2tf(f);
    l = __float_as_uint(f - __uint_as_float(h));
}
__device__ __forceinline__ void mma8(float* c, const u32* a, u32 b0, u32 b1) {
    asm volatile(
        "mma.sync.aligned.m16n8k8.row.col.f32.tf32.tf32.f32 "
        "{%0,%1,%2,%3}, {%4,%5,%6,%7}, {%8,%9}, {%0,%1,%2,%3};"
        : "+f"(c[0]), "+f"(c[1]), "+f"(c[2]), "+f"(c[3])
        : "r"(a[0]), "r"(a[1]), "r"(a[2]), "r"(a[3]), "r"(b0), "r"(b1));
}
__device__ __forceinline__ float elu(float v) {
    return v > 0.f ? v : (__expf(v) - 1.f);
}

// ---- prep: split weights into tf32 hi/lo, fragment-packed ----
__global__ void prep_kernel(
    const float* __restrict__ W1a, const float* __restrict__ W2a,
    const float* __restrict__ W1b, const float* __restrict__ W2b)
{
    int id = blockIdx.x * blockDim.x + threadIdx.x;   // 131072 total
    int lane = id & 31;
    int cell = (id >> 5) & 31;
    int b    = (id >> 10) & 31;
    int mat  = (id >> 15) & 1;
    int l    = id >> 16;
    int g = lane >> 2, t4 = lane & 3;
    float v0, v1;
    if (mat == 0) {
        int nt = cell >> 2, kt = cell & 3;
        int k0 = kt * 8 + t4, n = nt * 8 + g;
        const float* W = (l ? W1b : W1a) + b * 2048;
        v0 = W[k0 * 64 + n];
        v1 = W[(k0 + 4) * 64 + n];
    } else {
        int nt = cell >> 3, kt = cell & 7;
        int k0 = kt * 8 + t4, n = nt * 8 + g;
        const float* W = (l ? W2b : W2a) + b * 2048;
        v0 = W[k0 * 32 + n];
        v1 = W[(k0 + 4) * 32 + n];
    }
    float h0 = __uint_as_float(f2tf(v0));
    float h1 = __uint_as_float(f2tf(v1));
    int oi = (((l * 32 + b) * 32 + cell) * 32 + lane) * 2;
    float* hi = mat ? g_w2hi : g_w1hi;
    float* lo = mat ? g_w2lo : g_w1lo;
    hi[oi] = h0;      hi[oi + 1] = h1;
    lo[oi] = v0 - h0; lo[oi + 1] = v1 - h1;
}

// in-place per-row 32x32 block transpose; 8 warps x 2 rows = 16 rows
__device__ __forceinline__ void transpose_tile(float* tile, int warp, int lane) {
    const int a2 = lane >> 3;
    const int B  = lane & 7;
    #pragma unroll
    for (int rr = 0; rr < 2; ++rr) {
        float* row = tile + (warp * 2 + rr) * TS;
        float4 v[2][4];
        #pragma unroll
        for (int h = 0; h < 2; ++h) {
            int A = a2 + 4 * h;
            #pragma unroll
            for (int i = 0; i < 4; ++i)
                v[h][i] = *(const float4*)(row + 32 * (4 * A + i) + 4 * B);
        }
        __syncwarp();
        #pragma unroll
        for (int h = 0; h < 2; ++h) {
            int A = a2 + 4 * h;
            #pragma unroll
            for (int i = 0; i < 4; ++i) {
                float4 t;
                t.x = ((const float*)&v[h][0])[i];
                t.y = ((const float*)&v[h][1])[i];
                t.z = ((const float*)&v[h][2])[i];
                t.w = ((const float*)&v[h][3])[i];
                *(float4*)(row + 32 * (4 * B + i) + 4 * A) = t;
            }
        }
        __syncwarp();
    }
}

__global__ __launch_bounds__(NTHREADS, 2) void mixer_kernel(
    const float* __restrict__ x,
    const float* __restrict__ B1a, const float* __restrict__ B2a,
    const float* __restrict__ B1b, const float* __restrict__ B2b,
    float* __restrict__ out)
{
    extern __shared__ float smem[];
    float* tile = smem + SM_TILE;

    const int tid  = threadIdx.x;
    const int warp = tid >> 5;
    const int lane = tid & 31;
    const int g    = lane >> 2;
    const int t4   = lane & 3;
    const long row0 = (long)blockIdx.x * ROWS;

    float* hb = smem + SM_HB + warp * 1088;   // warp-private h staging

    const float* B1p[2] = {B1a, B1b};
    const float* B2p[2] = {B2a, B2b};

    // ---- load x tile (coalesced float4) ----
    {
        const float4* src = (const float4*)(x + row0 * 1024);
        #pragma unroll
        for (int it = 0; it < 16; ++it) {
            int i = tid + it * NTHREADS;
            int r = i >> 8, c4 = i & 255;
            *(float4*)(tile + r * TS + c4 * 4) = src[r * 256 + c4];
        }
    }
    __syncthreads();

    #pragma unroll 1
    for (int si = 0; si < 8; ++si) {
        if (si == 4) {                       // layer boundary
            __syncthreads();
            transpose_tile(tile, warp, lane);
            __syncthreads();
        }
        const int layer = si >> 2;
        const int blk   = (si & 3) * 8 + warp;   // this warp's block
        const int lb    = layer * 32 + blk;
        const int cbase = blk * 32;

        const u64* hi1 = (const u64*)(g_w1hi + (size_t)lb * 2048) + lane;
        const u64* lo1 = (const u64*)(g_w1lo + (size_t)lb * 2048) + lane;
        const u64* hi2 = (const u64*)(g_w2hi + (size_t)lb * 2048) + lane;
        const u64* lo2 = (const u64*)(g_w2lo + (size_t)lb * 2048) + lane;

        // ---- A-fragments (x split), rows g and g+8 ----
        u32 ah[4][4], al[4][4];
        {
            const float* xr = tile + g * TS + cbase;
            #pragma unroll
            for (int kt = 0; kt < 4; ++kt) {
                split(xr[kt * 8 + t4],              ah[kt][0], al[kt][0]);
                split(xr[8 * TS + kt * 8 + t4],     ah[kt][1], al[kt][1]);
                split(xr[kt * 8 + t4 + 4],          ah[kt][2], al[kt][2]);
                split(xr[8 * TS + kt * 8 + t4 + 4], ah[kt][3], al[kt][3]);
            }
        }

        // ---- matmul1: 16 rows x 64 hidden ----
        float c1[8][4];
        {
            const u64* b1q = (const u64*)(B1p[layer] + blk * 64);
            #pragma unroll
            for (int nt = 0; nt < 8; ++nt) {
                float blo, bhi;
                unpack2(b1q[nt * 4 + t4], blo, bhi);
                c1[nt][0] = blo; c1[nt][1] = bhi; c1[nt][2] = blo; c1[nt][3] = bhi;
            }
        }
        #pragma unroll
        for (int nt = 0; nt < 8; ++nt) {
            u64 bhf[4], blf[4];
            #pragma unroll
            for (int kt = 0; kt < 4; ++kt) {
                bhf[kt] = hi1[(nt * 4 + kt) * 32];
                blf[kt] = lo1[(nt * 4 + kt) * 32];
            }
            #pragma unroll
            for (int kt = 0; kt < 4; ++kt) {
                u32 bh0 = (u32)bhf[kt], bh1 = (u32)(bhf[kt] >> 32);
                u32 bl0 = (u32)blf[kt], bl1 = (u32)(blf[kt] >> 32);
                mma8(c1[nt], ah[kt], bh0, bh1);
                mma8(c1[nt], al[kt], bh0, bh1);
                mma8(c1[nt], ah[kt], bl0, bl1);
            }
        }

        // ---- ELU + stage h (warp-private) ----
        #pragma unroll
        for (int nt = 0; nt < 8; ++nt) {
            float e0 = elu(c1[nt][0]), e1 = elu(c1[nt][1]);
            float e2 = elu(c1[nt][2]), e3 = elu(c1[nt][3]);
            *(u64*)(hb + g * HS + nt * 8 + 2 * t4)       = pack2(e0, e1);
            *(u64*)(hb + (g + 8) * HS + nt * 8 + 2 * t4) = pack2(e2, e3);
        }
        __syncwarp();

        // ---- matmul2: 16 rows x 32 out (+bias+residual) ----
        float c2[4][4];
        {
            const u64* b2q = (const u64*)(B2p[layer] + blk * 32);
            const float* resp = tile + g * TS + cbase;
            #pragma unroll
            for (int nt = 0; nt < 4; ++nt) {
                float blo, bhi, r0l, r0h, r1l, r1h;
                unpack2(b2q[nt * 4 + t4], blo, bhi);
                unpack2(*(const u64*)(resp + nt * 8 + 2 * t4), r0l, r0h);
                unpack2(*(const u64*)(resp + 8 * TS + nt * 8 + 2 * t4), r1l, r1h);
                c2[nt][0] = blo + r0l; c2[nt][1] = bhi + r0h;
                c2[nt][2] = blo + r1l; c2[nt][3] = bhi + r1h;
            }
        }
        #pragma unroll
        for (int kt = 0; kt < 8; ++kt) {
            u32 ah2[4], al2[4];
            split(hb[g * HS + kt * 8 + t4],            ah2[0], al2[0]);
            split(hb[(g + 8) * HS + kt * 8 + t4],      ah2[1], al2[1]);
            split(hb[g * HS + kt * 8 + t4 + 4],        ah2[2], al2[2]);
            split(hb[(g + 8) * HS + kt * 8 + t4 + 4],  ah2[3], al2[3]);
            u64 bhf[4], blf[4];
            #pragma unroll
            for (int nt = 0; nt < 4; ++nt) {
                bhf[nt] = hi2[(nt * 8 + kt) * 32];
                blf[nt] = lo2[(nt * 8 + kt) * 32];
            }
            #pragma unroll
            for (int nt = 0; nt < 4; ++nt) {
                u32 bh0 = (u32)bhf[nt], bh1 = (u32)(bhf[nt] >> 32);
                u32 bl0 = (u32)blf[nt], bl1 = (u32)(blf[nt] >> 32);
                mma8(c2[nt], ah2, bh0, bh1);
                mma8(c2[nt], al2, bh0, bh1);
                mma8(c2[nt], ah2, bl0, bl1);
            }
        }
        {
            float* resp = tile + g * TS + cbase;
            #pragma unroll
            for (int nt = 0; nt < 4; ++nt) {
                *(u64*)(resp + nt * 8 + 2 * t4)          = pack2(c2[nt][0], c2[nt][1]);
                *(u64*)(resp + 8 * TS + nt * 8 + 2 * t4) = pack2(c2[nt][2], c2[nt][3]);
            }
        }
        // no barrier: within a layer, each block's columns are owned by one warp
    }

    __syncthreads();
    transpose_tile(tile, warp, lane);        // undo layer-1 permutation
    __syncthreads();

    // ---- store output (coalesced float4) ----
    {
        float4* dst = (float4*)(out + row0 * 1024);
        #pragma unroll
        for (int it = 0; it < 16; ++it) {
            int i = tid + it * NTHREADS;
            int r = i >> 8, c4 = i & 255;
            dst[r * 256 + c4] = *(const float4*)(tile + r * TS + c4 * 4);
        }
    }
}

extern "C" void kernel_launch(void* const* d_in, const int* in_sizes, int n_in,
                              void* d_out, int out_size) {
    const float* x   = (const float*)d_in[0];
    const float* W1a = (const float*)d_in[1];
    const float* B1a = (const float*)d_in[2];
    const float* W2a = (const float*)d_in[3];
    const float* B2a = (const float*)d_in[4];
    const float* W1b = (const float*)d_in[5];
    const float* B1b = (const float*)d_in[6];
    const float* W2b = (const float*)d_in[7];
    const float* B2b = (const float*)d_in[8];
    float* out = (float*)d_out;

    int rows = in_sizes[0] / 1024;
    int grid = rows / ROWS;                    // 1024

    size_t smem_bytes = (size_t)SM_TOTAL * sizeof(float);   // 100608 B
    static int configured = -1;
    if (configured < 0) {
        cudaFuncSetAttribute(mixer_kernel,
                             cudaFuncAttributeMaxDynamicSharedMemorySize,
                             (int)smem_bytes);
        configured = 1;
    }

    prep_kernel<<<512, 256>>>(W1a, W2a, W1b, W2b);
    mixer_kernel<<<grid, NTHREADS, smem_bytes>>>(
        x, B1a, B2a, B1b, B2b, out);
}

// round 9
// speedup vs baseline: 1.7236x; 1.0880x over previous
#include <cuda_runtime.h>

#define NTHREADS 256
#define TS 1028                  // tile row stride
#define HS 68                    // hbuf row stride
#define ROWS 16

#define SM_TILE 0
#define SM_HB   16448            // 16*1028
#define SM_TOTAL (SM_HB + 8 * 1088)   // 25152 floats = 100608 B

typedef unsigned long long u64;
typedef unsigned int u32;

// fragment-packed bf16 split weights: [layer*32+block][cell 16][lane 32] -> {h0,h1,l0,l1}
__device__ uint4 g_w1[2 * 32 * 16 * 32];
__device__ uint4 g_w2[2 * 32 * 16 * 32];

__device__ __forceinline__ u64 pack2(float lo, float hi) {
    u64 r; asm("mov.b64 %0, {%1, %2};" : "=l"(r) : "f"(lo), "f"(hi)); return r;
}
__device__ __forceinline__ void unpack2(u64 v, float& lo, float& hi) {
    asm("mov.b64 {%0, %1}, %2;" : "=f"(lo), "=f"(hi) : "l"(v));
}
__device__ __forceinline__ u32 bpack(float lo, float hi) {
    u32 r; asm("cvt.rn.bf16x2.f32 %0, %1, %2;" : "=r"(r) : "f"(hi), "f"(lo)); return r;
}
__device__ __forceinline__ float blof(u32 w) { return __uint_as_float(w << 16); }
__device__ __forceinline__ float bhif(u32 w) { return __uint_as_float(w & 0xFFFF0000u); }
__device__ __forceinline__ void bsplit2(float x0, float x1, u32& h, u32& l) {
    h = bpack(x0, x1);
    l = bpack(x0 - blof(h), x1 - bhif(h));
}
__device__ __forceinline__ void mma16(float* c, const u32* a, u32 b0, u32 b1) {
    asm volatile(
        "mma.sync.aligned.m16n8k16.row.col.f32.bf16.bf16.f32 "
        "{%0,%1,%2,%3}, {%4,%5,%6,%7}, {%8,%9}, {%0,%1,%2,%3};"
        : "+f"(c[0]), "+f"(c[1]), "+f"(c[2]), "+f"(c[3])
        : "r"(a[0]), "r"(a[1]), "r"(a[2]), "r"(a[3]), "r"(b0), "r"(b1));
}
__device__ __forceinline__ float elu(float v) {
    return v > 0.f ? v : (__expf(v) - 1.f);
}

// ---- prep: split weights into bf16 hi/lo, fragment-packed uint4 cells ----
__global__ void prep_kernel(
    const float* __restrict__ W1a, const float* __restrict__ W2a,
    const float* __restrict__ W1b, const float* __restrict__ W2b)
{
    int id = blockIdx.x * blockDim.x + threadIdx.x;   // 65536 total
    int lane = id & 31;
    int cell = (id >> 5) & 15;
    int b    = (id >> 9) & 31;
    int mat  = (id >> 14) & 1;
    int l    = (id >> 15) & 1;
    int g = lane >> 2, t4 = lane & 3;

    float f00, f01, f10, f11;
    if (mat == 0) {
        int nt = cell >> 1, kt = cell & 1;
        int k0 = kt * 16 + 2 * t4, n = nt * 8 + g;
        const float* W = (l ? W1b : W1a) + b * 2048;
        f00 = W[k0 * 64 + n];       f01 = W[(k0 + 1) * 64 + n];
        f10 = W[(k0 + 8) * 64 + n]; f11 = W[(k0 + 9) * 64 + n];
    } else {
        int nt = cell >> 2, kt = cell & 3;
        int k0 = kt * 16 + 2 * t4, n = nt * 8 + g;
        const float* W = (l ? W2b : W2a) + b * 2048;
        f00 = W[k0 * 32 + n];       f01 = W[(k0 + 1) * 32 + n];
        f10 = W[(k0 + 8) * 32 + n]; f11 = W[(k0 + 9) * 32 + n];
    }
    u32 h0, l0, h1, l1;
    bsplit2(f00, f01, h0, l0);
    bsplit2(f10, f11, h1, l1);
    uint4 v; v.x = h0; v.y = h1; v.z = l0; v.w = l1;
    uint4* dst = mat ? g_w2 : g_w1;
    dst[((l * 32 + b) * 16 + cell) * 32 + lane] = v;
}

// in-place per-row 32x32 block transpose; 8 warps x 2 rows
__device__ __forceinline__ void transpose_tile(float* tile, int warp, int lane) {
    const int a2 = lane >> 3;
    const int B  = lane & 7;
    #pragma unroll
    for (int rr = 0; rr < 2; ++rr) {
        float* row = tile + (warp * 2 + rr) * TS;
        float4 v[2][4];
        #pragma unroll
        for (int h = 0; h < 2; ++h) {
            int A = a2 + 4 * h;
            #pragma unroll
            for (int i = 0; i < 4; ++i)
                v[h][i] = *(const float4*)(row + 32 * (4 * A + i) + 4 * B);
        }
        __syncwarp();
        #pragma unroll
        for (int h = 0; h < 2; ++h) {
            int A = a2 + 4 * h;
            #pragma unroll
            for (int i = 0; i < 4; ++i) {
                float4 t;
                t.x = ((const float*)&v[h][0])[i];
                t.y = ((const float*)&v[h][1])[i];
                t.z = ((const float*)&v[h][2])[i];
                t.w = ((const float*)&v[h][3])[i];
                *(float4*)(row + 32 * (4 * B + i) + 4 * A) = t;
            }
        }
        __syncwarp();
    }
}

__global__ __launch_bounds__(NTHREADS, 2) void mixer_kernel(
    const float* __restrict__ x,
    const float* __restrict__ B1a, const float* __restrict__ B2a,
    const float* __restrict__ B1b, const float* __restrict__ B2b,
    float* __restrict__ out)
{
    extern __shared__ float smem[];
    float* tile = smem + SM_TILE;

    const int tid  = threadIdx.x;
    const int warp = tid >> 5;
    const int lane = tid & 31;
    const int g    = lane >> 2;
    const int t4   = lane & 3;
    const long row0 = (long)blockIdx.x * ROWS;

    float* hb = smem + SM_HB + warp * 1088;   // warp-private h staging

    const float* B1p[2] = {B1a, B1b};
    const float* B2p[2] = {B2a, B2b};

    // ---- load x tile ----
    {
        const float4* src = (const float4*)(x + row0 * 1024);
        #pragma unroll
        for (int it = 0; it < 16; ++it) {
            int i = tid + it * NTHREADS;
            int r = i >> 8, c4 = i & 255;
            *(float4*)(tile + r * TS + c4 * 4) = src[r * 256 + c4];
        }
    }
    __syncthreads();

    #pragma unroll 1
    for (int si = 0; si < 8; ++si) {
        if (si == 4) {                       // layer boundary
            __syncthreads();
            transpose_tile(tile, warp, lane);
            __syncthreads();
        }
        const int layer = si >> 2;
        const int blk   = (si & 3) * 8 + warp;
        const int lb    = layer * 32 + blk;
        const int cbase = blk * 32;

        const uint4* w1q = g_w1 + (size_t)lb * 512 + lane;
        const uint4* w2q = g_w2 + (size_t)lb * 512 + lane;

        // ---- A-fragments: bf16 split of x, rows g and g+8 ----
        u32 xh[2][4], xl[2][4];
        {
            const float* xr = tile + g * TS + cbase;
            #pragma unroll
            for (int kt = 0; kt < 2; ++kt) {
                int c0 = kt * 16 + 2 * t4;
                float2 v0 = *(const float2*)(xr + c0);
                float2 v1 = *(const float2*)(xr + 8 * TS + c0);
                float2 v2 = *(const float2*)(xr + c0 + 8);
                float2 v3 = *(const float2*)(xr + 8 * TS + c0 + 8);
                bsplit2(v0.x, v0.y, xh[kt][0], xl[kt][0]);
                bsplit2(v1.x, v1.y, xh[kt][1], xl[kt][1]);
                bsplit2(v2.x, v2.y, xh[kt][2], xl[kt][2]);
                bsplit2(v3.x, v3.y, xh[kt][3], xl[kt][3]);
            }
        }

        // ---- matmul1: 16 rows x 64 hidden ----
        float c1[8][4];
        {
            const u64* b1q = (const u64*)(B1p[layer] + blk * 64);
            #pragma unroll
            for (int nt = 0; nt < 8; ++nt) {
                float blo, bhi;
                unpack2(b1q[nt * 4 + t4], blo, bhi);
                c1[nt][0] = blo; c1[nt][1] = bhi; c1[nt][2] = blo; c1[nt][3] = bhi;
            }
        }
        #pragma unroll
        for (int nt = 0; nt < 8; ++nt) {
            uint4 B0 = w1q[(nt * 2 + 0) * 32];
            uint4 B1 = w1q[(nt * 2 + 1) * 32];
            mma16(c1[nt], xh[0], B0.x, B0.y);
            mma16(c1[nt], xl[0], B0.x, B0.y);
            mma16(c1[nt], xh[0], B0.z, B0.w);
            mma16(c1[nt], xh[1], B1.x, B1.y);
            mma16(c1[nt], xl[1], B1.x, B1.y);
            mma16(c1[nt], xh[1], B1.z, B1.w);
        }

        // ---- ELU + stage h (warp-private, fp32) ----
        #pragma unroll
        for (int nt = 0; nt < 8; ++nt) {
            float e0 = elu(c1[nt][0]), e1 = elu(c1[nt][1]);
            float e2 = elu(c1[nt][2]), e3 = elu(c1[nt][3]);
            *(u64*)(hb + g * HS + nt * 8 + 2 * t4)       = pack2(e0, e1);
            *(u64*)(hb + (g + 8) * HS + nt * 8 + 2 * t4) = pack2(e2, e3);
        }
        __syncwarp();

        // ---- matmul2: 16 rows x 32 out (+bias+residual) ----
        float c2[4][4];
        {
            const u64* b2q = (const u64*)(B2p[layer] + blk * 32);
            const float* resp = tile + g * TS + cbase;
            #pragma unroll
            for (int nt = 0; nt < 4; ++nt) {
                float blo, bhi, r0l, r0h, r1l, r1h;
                unpack2(b2q[nt * 4 + t4], blo, bhi);
                unpack2(*(const u64*)(resp + nt * 8 + 2 * t4), r0l, r0h);
                unpack2(*(const u64*)(resp + 8 * TS + nt * 8 + 2 * t4), r1l, r1h);
                c2[nt][0] = blo + r0l; c2[nt][1] = bhi + r0h;
                c2[nt][2] = blo + r1l; c2[nt][3] = bhi + r1h;
            }
        }
        #pragma unroll
        for (int kt = 0; kt < 4; ++kt) {
            u32 hh[4], hl[4];
            {
                int c0 = kt * 16 + 2 * t4;
                float2 v0 = *(const float2*)(hb + g * HS + c0);
                float2 v1 = *(const float2*)(hb + (g + 8) * HS + c0);
                float2 v2 = *(const float2*)(hb + g * HS + c0 + 8);
                float2 v3 = *(const float2*)(hb + (g + 8) * HS + c0 + 8);
                bsplit2(v0.x, v0.y, hh[0], hl[0]);
                bsplit2(v1.x, v1.y, hh[1], hl[1]);
                bsplit2(v2.x, v2.y, hh[2], hl[2]);
                bsplit2(v3.x, v3.y, hh[3], hl[3]);
            }
            #pragma unroll
            for (int nt = 0; nt < 4; ++nt) {
                uint4 B = w2q[(nt * 4 + kt) * 32];
                mma16(c2[nt], hh, B.x, B.y);
                mma16(c2[nt], hl, B.x, B.y);
                mma16(c2[nt], hh, B.z, B.w);
            }
        }
        {
            float* resp = tile + g * TS + cbase;
            #pragma unroll
            for (int nt = 0; nt < 4; ++nt) {
                *(u64*)(resp + nt * 8 + 2 * t4)          = pack2(c2[nt][0], c2[nt][1]);
                *(u64*)(resp + 8 * TS + nt * 8 + 2 * t4) = pack2(c2[nt][2], c2[nt][3]);
            }
        }
    }

    __syncthreads();
    transpose_tile(tile, warp, lane);        // undo layer-1 permutation
    __syncthreads();

    // ---- store output ----
    {
        float4* dst = (float4*)(out + row0 * 1024);
        #pragma unroll
        for (int it = 0; it < 16; ++it) {
            int i = tid + it * NTHREADS;
            int r = i >> 8, c4 = i & 255;
            dst[r * 256 + c4] = *(const float4*)(tile + r * TS + c4 * 4);
        }
    }
}

extern "C" void kernel_launch(void* const* d_in, const int* in_sizes, int n_in,
                              void* d_out, int out_size) {
    const float* x   = (const float*)d_in[0];
    const float* W1a = (const float*)d_in[1];
    const float* B1a = (const float*)d_in[2];
    const float* W2a = (const float*)d_in[3];
    const float* B2a = (const float*)d_in[4];
    const float* W1b = (const float*)d_in[5];
    const float* B1b = (const float*)d_in[6];
    const float* W2b = (const float*)d_in[7];
    const float* B2b = (const float*)d_in[8];
    float* out = (float*)d_out;

    int rows = in_sizes[0] / 1024;
    int grid = rows / ROWS;                    // 1024

    size_t smem_bytes = (size_t)SM_TOTAL * sizeof(float);   // 100608 B
    static int configured = -1;
    if (configured < 0) {
        cudaFuncSetAttribute(mixer_kernel,
                             cudaFuncAttributeMaxDynamicSharedMemorySize,
                             (int)smem_bytes);
        configured = 1;
    }

    prep_kernel<<<256, 256>>>(W1a, W2a, W1b, W2b);
    mixer_kernel<<<grid, NTHREADS, smem_bytes>>>(
        x, B1a, B2a, B1b, B2b, out);
}

// round 10
// speedup vs baseline: 2.0886x; 1.2118x over previous
#include <cuda_runtime.h>

#define NTHREADS 256
#define TS 1028                  // tile row stride
#define ROWS 16

#define SM_TOTAL 16448           // 16*1028 floats = 65792 B

typedef unsigned long long u64;
typedef unsigned int u32;

// fragment-packed bf16 split weights: [layer*32+block][cell 16][lane 32] -> {h0,h1,l0,l1}
__device__ uint4 g_w1[2 * 32 * 16 * 32];
__device__ uint4 g_w2[2 * 32 * 16 * 32];

__device__ __forceinline__ u64 pack2(float lo, float hi) {
    u64 r; asm("mov.b64 %0, {%1, %2};" : "=l"(r) : "f"(lo), "f"(hi)); return r;
}
__device__ __forceinline__ void unpack2(u64 v, float& lo, float& hi) {
    asm("mov.b64 {%0, %1}, %2;" : "=f"(lo), "=f"(hi) : "l"(v));
}
__device__ __forceinline__ u32 bpack(float lo, float hi) {
    u32 r; asm("cvt.rn.bf16x2.f32 %0, %1, %2;" : "=r"(r) : "f"(hi), "f"(lo)); return r;
}
__device__ __forceinline__ float blof(u32 w) { return __uint_as_float(w << 16); }
__device__ __forceinline__ float bhif(u32 w) { return __uint_as_float(w & 0xFFFF0000u); }
__device__ __forceinline__ void bsplit2(float x0, float x1, u32& h, u32& l) {
    h = bpack(x0, x1);
    l = bpack(x0 - blof(h), x1 - bhif(h));
}
__device__ __forceinline__ void mma16(float* c, const u32* a, u32 b0, u32 b1) {
    asm volatile(
        "mma.sync.aligned.m16n8k16.row.col.f32.bf16.bf16.f32 "
        "{%0,%1,%2,%3}, {%4,%5,%6,%7}, {%8,%9}, {%0,%1,%2,%3};"
        : "+f"(c[0]), "+f"(c[1]), "+f"(c[2]), "+f"(c[3])
        : "r"(a[0]), "r"(a[1]), "r"(a[2]), "r"(a[3]), "r"(b0), "r"(b1));
}
__device__ __forceinline__ float elu(float v) {
    return v > 0.f ? v : (__expf(v) - 1.f);
}

// ---- prep: split weights into bf16 hi/lo, fragment-packed uint4 cells ----
__global__ void prep_kernel(
    const float* __restrict__ W1a, const float* __restrict__ W2a,
    const float* __restrict__ W1b, const float* __restrict__ W2b)
{
    int id = blockIdx.x * blockDim.x + threadIdx.x;   // 65536 total
    int lane = id & 31;
    int cell = (id >> 5) & 15;
    int b    = (id >> 9) & 31;
    int mat  = (id >> 14) & 1;
    int l    = (id >> 15) & 1;
    int g = lane >> 2, t4 = lane & 3;

    float f00, f01, f10, f11;
    if (mat == 0) {
        int nt = cell >> 1, kt = cell & 1;
        int k0 = kt * 16 + 2 * t4, n = nt * 8 + g;
        const float* W = (l ? W1b : W1a) + b * 2048;
        f00 = W[k0 * 64 + n];       f01 = W[(k0 + 1) * 64 + n];
        f10 = W[(k0 + 8) * 64 + n]; f11 = W[(k0 + 9) * 64 + n];
    } else {
        int nt = cell >> 2, kt = cell & 3;
        int k0 = kt * 16 + 2 * t4, n = nt * 8 + g;
        const float* W = (l ? W2b : W2a) + b * 2048;
        f00 = W[k0 * 32 + n];       f01 = W[(k0 + 1) * 32 + n];
        f10 = W[(k0 + 8) * 32 + n]; f11 = W[(k0 + 9) * 32 + n];
    }
    u32 h0, l0, h1, l1;
    bsplit2(f00, f01, h0, l0);
    bsplit2(f10, f11, h1, l1);
    uint4 v; v.x = h0; v.y = h1; v.z = l0; v.w = l1;
    uint4* dst = mat ? g_w2 : g_w1;
    dst[((l * 32 + b) * 16 + cell) * 32 + lane] = v;
}

// in-place per-row 32x32 block transpose; 8 warps x 2 rows
__device__ __forceinline__ void transpose_tile(float* tile, int warp, int lane) {
    const int a2 = lane >> 3;
    const int B  = lane & 7;
    #pragma unroll
    for (int rr = 0; rr < 2; ++rr) {
        float* row = tile + (warp * 2 + rr) * TS;
        float4 v[2][4];
        #pragma unroll
        for (int h = 0; h < 2; ++h) {
            int A = a2 + 4 * h;
            #pragma unroll
            for (int i = 0; i < 4; ++i)
                v[h][i] = *(const float4*)(row + 32 * (4 * A + i) + 4 * B);
        }
        __syncwarp();
        #pragma unroll
        for (int h = 0; h < 2; ++h) {
            int A = a2 + 4 * h;
            #pragma unroll
            for (int i = 0; i < 4; ++i) {
                float4 t;
                t.x = ((const float*)&v[h][0])[i];
                t.y = ((const float*)&v[h][1])[i];
                t.z = ((const float*)&v[h][2])[i];
                t.w = ((const float*)&v[h][3])[i];
                *(float4*)(row + 32 * (4 * B + i) + 4 * A) = t;
            }
        }
        __syncwarp();
    }
}

__global__ __launch_bounds__(NTHREADS, 2) void mixer_kernel(
    const float* __restrict__ x,
    const float* __restrict__ B1a, const float* __restrict__ B2a,
    const float* __restrict__ B1b, const float* __restrict__ B2b,
    float* __restrict__ out)
{
    extern __shared__ float smem[];
    float* tile = smem;

    const int tid  = threadIdx.x;
    const int warp = tid >> 5;
    const int lane = tid & 31;
    const int g    = lane >> 2;
    const int t4   = lane & 3;
    const long row0 = (long)blockIdx.x * ROWS;

    const float* B1p[2] = {B1a, B1b};
    const float* B2p[2] = {B2a, B2b};

    // ---- load x tile ----
    {
        const float4* src = (const float4*)(x + row0 * 1024);
        #pragma unroll
        for (int it = 0; it < 16; ++it) {
            int i = tid + it * NTHREADS;
            int r = i >> 8, c4 = i & 255;
            *(float4*)(tile + r * TS + c4 * 4) = src[r * 256 + c4];
        }
    }
    __syncthreads();

    #pragma unroll 1
    for (int si = 0; si < 8; ++si) {
        if (si == 4) {                       // layer boundary
            __syncthreads();
            transpose_tile(tile, warp, lane);
            __syncthreads();
        }
        const int layer = si >> 2;
        const int blk   = (si & 3) * 8 + warp;
        const int lb    = layer * 32 + blk;
        const int cbase = blk * 32;

        const uint4* w1q = g_w1 + (size_t)lb * 512 + lane;
        const uint4* w2q = g_w2 + (size_t)lb * 512 + lane;

        // ---- A-fragments: bf16 split of x; keep fp32 copies for residual ----
        u32 xh[2][4], xl[2][4];
        float2 res[2][4];
        {
            const float* xr = tile + g * TS + cbase;
            #pragma unroll
            for (int kt = 0; kt < 2; ++kt) {
                int c0 = kt * 16 + 2 * t4;
                res[kt][0] = *(const float2*)(xr + c0);
                res[kt][1] = *(const float2*)(xr + 8 * TS + c0);
                res[kt][2] = *(const float2*)(xr + c0 + 8);
                res[kt][3] = *(const float2*)(xr + 8 * TS + c0 + 8);
                bsplit2(res[kt][0].x, res[kt][0].y, xh[kt][0], xl[kt][0]);
                bsplit2(res[kt][1].x, res[kt][1].y, xh[kt][1], xl[kt][1]);
                bsplit2(res[kt][2].x, res[kt][2].y, xh[kt][2], xl[kt][2]);
                bsplit2(res[kt][3].x, res[kt][3].y, xh[kt][3], xl[kt][3]);
            }
        }

        // ---- matmul1: 16 rows x 64 hidden ----
        float c1[8][4];
        {
            const u64* b1q = (const u64*)(B1p[layer] + blk * 64);
            #pragma unroll
            for (int nt = 0; nt < 8; ++nt) {
                float blo, bhi;
                unpack2(b1q[nt * 4 + t4], blo, bhi);
                c1[nt][0] = blo; c1[nt][1] = bhi; c1[nt][2] = blo; c1[nt][3] = bhi;
            }
        }
        #pragma unroll
        for (int nt = 0; nt < 8; ++nt) {
            uint4 B0 = w1q[(nt * 2 + 0) * 32];
            uint4 B1 = w1q[(nt * 2 + 1) * 32];
            mma16(c1[nt], xh[0], B0.x, B0.y);
            mma16(c1[nt], xl[0], B0.x, B0.y);
            mma16(c1[nt], xh[0], B0.z, B0.w);
            mma16(c1[nt], xh[1], B1.x, B1.y);
            mma16(c1[nt], xl[1], B1.x, B1.y);
            mma16(c1[nt], xh[1], B1.z, B1.w);
        }

        // ---- ELU in registers, then rebuild mm2 A-fragments directly ----
        // c1 fragment layout (rows {g,g+8} x cols {8nt+2t4,+1}) IS the mm2
        // A-fragment layout: k-chunk kt uses c1[2kt] (k-local 2t4) and
        // c1[2kt+1] (k-local 8+2t4).
        u32 a2h[4][4], a2l[4][4];
        #pragma unroll
        for (int nt = 0; nt < 8; ++nt) {
            c1[nt][0] = elu(c1[nt][0]); c1[nt][1] = elu(c1[nt][1]);
            c1[nt][2] = elu(c1[nt][2]); c1[nt][3] = elu(c1[nt][3]);
        }
        #pragma unroll
        for (int kt = 0; kt < 4; ++kt) {
            bsplit2(c1[2 * kt][0],     c1[2 * kt][1],     a2h[kt][0], a2l[kt][0]);
            bsplit2(c1[2 * kt][2],     c1[2 * kt][3],     a2h[kt][1], a2l[kt][1]);
            bsplit2(c1[2 * kt + 1][0], c1[2 * kt + 1][1], a2h[kt][2], a2l[kt][2]);
            bsplit2(c1[2 * kt + 1][2], c1[2 * kt + 1][3], a2h[kt][3], a2l[kt][3]);
        }

        // ---- matmul2: 16 rows x 32 out; bias + residual from registers ----
        float c2[4][4];
        {
            const u64* b2q = (const u64*)(B2p[layer] + blk * 32);
            #pragma unroll
            for (int nt = 0; nt < 4; ++nt) {
                float blo, bhi;
                unpack2(b2q[nt * 4 + t4], blo, bhi);
                const float2 rl = res[nt >> 1][(nt & 1) * 2];      // row g
                const float2 rh = res[nt >> 1][(nt & 1) * 2 + 1];  // row g+8
                c2[nt][0] = blo + rl.x; c2[nt][1] = bhi + rl.y;
                c2[nt][2] = blo + rh.x; c2[nt][3] = bhi + rh.y;
            }
        }
        #pragma unroll
        for (int kt = 0; kt < 4; ++kt) {
            #pragma unroll
            for (int nt = 0; nt < 4; ++nt) {
                uint4 B = w2q[(nt * 4 + kt) * 32];
                mma16(c2[nt], a2h[kt], B.x, B.y);
                mma16(c2[nt], a2l[kt], B.x, B.y);
                mma16(c2[nt], a2h[kt], B.z, B.w);
            }
        }
        {
            float* resp = tile + g * TS + cbase;
            #pragma unroll
            for (int nt = 0; nt < 4; ++nt) {
                *(u64*)(resp + nt * 8 + 2 * t4)          = pack2(c2[nt][0], c2[nt][1]);
                *(u64*)(resp + 8 * TS + nt * 8 + 2 * t4) = pack2(c2[nt][2], c2[nt][3]);
            }
        }
    }

    __syncthreads();
    transpose_tile(tile, warp, lane);        // undo layer-1 permutation
    __syncthreads();

    // ---- store output ----
    {
        float4* dst = (float4*)(out + row0 * 1024);
        #pragma unroll
        for (int it = 0; it < 16; ++it) {
            int i = tid + it * NTHREADS;
            int r = i >> 8, c4 = i & 255;
            dst[r * 256 + c4] = *(const float4*)(tile + r * TS + c4 * 4);
        }
    }
}

extern "C" void kernel_launch(void* const* d_in, const int* in_sizes, int n_in,
                              void* d_out, int out_size) {
    const float* x   = (const float*)d_in[0];
    const float* W1a = (const float*)d_in[1];
    const float* B1a = (const float*)d_in[2];
    const float* W2a = (const float*)d_in[3];
    const float* B2a = (const float*)d_in[4];
    const float* W1b = (const float*)d_in[5];
    const float* B1b = (const float*)d_in[6];
    const float* W2b = (const float*)d_in[7];
    const float* B2b = (const float*)d_in[8];
    float* out = (float*)d_out;

    int rows = in_sizes[0] / 1024;
    int grid = rows / ROWS;                    // 1024

    size_t smem_bytes = (size_t)SM_TOTAL * sizeof(float);   // 65792 B
    static int configured = -1;
    if (configured < 0) {
        cudaFuncSetAttribute(mixer_kernel,
                             cudaFuncAttributeMaxDynamicSharedMemorySize,
                             (int)smem_bytes);
        configured = 1;
    }

    prep_kernel<<<256, 256>>>(W1a, W2a, W1b, W2b);
    mixer_kernel<<<grid, NTHREADS, smem_bytes>>>(
        x, B1a, B2a, B1b, B2b, out);
}